// round 2
// baseline (speedup 1.0000x reference)
#include <cuda_runtime.h>

#define BB 32
#define NN 1024
#define FF 128
#define HH 64
#define CC 32
#define KK 2
#define NITER 5
#define INV_TEMP 2.0f
#define ROWS (BB*NN)
#define FULLM 0xffffffffu

// ---------------- scratch (device globals; allocation-free) ----------------
__device__ float    g_dY[ROWS*HH];     // dinv_j * (x @ W_gcn)[j,:]
__device__ float    g_dinv[ROWS];
__device__ unsigned g_adjb[ROWS*32];   // bit-packed adjacency rows
__device__ unsigned g_adjl[ROWS*32];   // bit-packed 2-hop reachability
__device__ float    g_h[ROWS*HH];
__device__ float    g_unary[ROWS*CC];
__device__ float    g_e[ROWS*KK];
__device__ float    g_Q[ROWS*CC];
__device__ float    g_Y[ROWS*64];      // Y[j][k*32+c] = e[j][k] * (Q@mu)[j][c]
__device__ float    g_cs[BB*64];       // per-batch column sums of Y
__device__ float    g_AQ[ROWS*CC];     // adj @ Q

// ------------- K1: pack adjacency bits + degree -> dinv ---------------------
__global__ void k_bits(const int* __restrict__ adj) {
    int warp = threadIdx.x >> 5, lane = threadIdx.x & 31;
    int row  = blockIdx.x * 8 + warp;
    const int* ar = adj + (size_t)row * NN;
    unsigned myw = 0;
#pragma unroll
    for (int w = 0; w < 32; w++) {
        unsigned bal = __ballot_sync(FULLM, ar[(w << 5) + lane] != 0);
        if (lane == w) myw = bal;
    }
    g_adjb[row * 32 + lane] = myw;
    int d = __popc(myw);
#pragma unroll
    for (int o = 16; o; o >>= 1) d += __shfl_xor_sync(FULLM, d, o);
    if (lane == 0) g_dinv[row] = rsqrtf((float)d + 1.0f);   // +1 self loop
}

// ------------- K2: xw = x @ W_gcn, scaled by dinv ---------------------------
__global__ void k_xw(const float* __restrict__ x, const float* __restrict__ Wg) {
    __shared__ float Ws[FF * HH];
    for (int i = threadIdx.x; i < FF * HH; i += 256) Ws[i] = Wg[i];
    __syncthreads();
    int warp = threadIdx.x >> 5, lane = threadIdx.x & 31;
    for (int r = 0; r < 4; r++) {
        int row = blockIdx.x * 32 + warp * 4 + r;
        const float* xr = x + (size_t)row * FF;
        float a0 = 0.f, a1 = 0.f;
        for (int kb = 0; kb < FF; kb += 32) {
            float xv32 = xr[kb + lane];
#pragma unroll
            for (int t = 0; t < 32; t++) {
                float xv = __shfl_sync(FULLM, xv32, t);
                a0 += xv * Ws[(kb + t) * HH + lane];
                a1 += xv * Ws[(kb + t) * HH + lane + 32];
            }
        }
        float di = g_dinv[row];
        g_dY[(size_t)row * HH + lane]      = a0 * di;
        g_dY[(size_t)row * HH + lane + 32] = a1 * di;
    }
}

// ------------- K3: 2-hop reachability bitsets (OR of neighbor rows) ---------
__global__ void k_adjl() {
    int warp = threadIdx.x >> 5, lane = threadIdx.x & 31;
    int row  = blockIdx.x * 8 + warp;
    int base = (row >> 10) << 10;                 // batch start row
    unsigned myw = g_adjb[row * 32 + lane];
    unsigned acc = 0;
    for (int wk = 0; wk < 32; wk++) {
        unsigned bits = __shfl_sync(FULLM, myw, wk);
        while (bits) {
            int t = __ffs(bits) - 1; bits &= bits - 1;
            acc |= g_adjb[(size_t)(base + (wk << 5) + t) * 32 + lane];
        }
        if (__all_sync(FULLM, acc == FULLM)) break;   // saturated -> done
    }
    g_adjl[row * 32 + lane] = acc;
}

// ------------- K4: h = relu(dinv_i * (A_hat-sum of dY) + b) -----------------
__global__ void k_gcnagg(const float* __restrict__ bg) {
    extern __shared__ float sY[];                  // NN x 32 (one H-half)
    int b = blockIdx.x, half = blockIdx.y, chunk = blockIdx.z;
    const float* dYb = g_dY + (size_t)b * NN * HH + half * 32;
    for (int idx = threadIdx.x; idx < NN * 32; idx += blockDim.x)
        sY[idx] = dYb[(size_t)(idx >> 5) * HH + (idx & 31)];
    __syncthreads();
    int warp = threadIdx.x >> 5, lane = threadIdx.x & 31;
    float bias = bg[half * 32 + lane];
    for (int r = warp; r < 128; r += 16) {
        int i   = chunk * 128 + r;
        int row = b * NN + i;
        unsigned myw = g_adjb[row * 32 + lane];
        const float* sl = sY + lane;
        float acc = 0.f;
        for (int wk = 0; wk < 32; wk++) {
            unsigned bits = __shfl_sync(FULLM, myw, wk);
            int bse = wk << 5;
            while (bits) {
                int t = __ffs(bits) - 1; bits &= bits - 1;
                acc += sl[(bse + t) << 5];
            }
        }
        acc += sl[i << 5];                         // +I self loop
        float hv = fmaf(g_dinv[row], acc, bias);
        g_h[(size_t)row * HH + half * 32 + lane] = fmaxf(hv, 0.f);
    }
}

// ------------- K5: unary = h @ W_unary + b; e = exp(-||(h-m)/s||^2) ---------
__global__ void k_unary_e(const float* __restrict__ Wu, const float* __restrict__ bu,
                          const float* __restrict__ means, const float* __restrict__ scales) {
    __shared__ float sW[HH * CC];
    __shared__ float sM[KK * HH], sS[KK * HH];
    for (int i = threadIdx.x; i < HH * CC; i += 256) sW[i] = Wu[i];
    for (int i = threadIdx.x; i < KK * HH; i += 256) { sM[i] = means[i]; sS[i] = scales[i]; }
    __syncthreads();
    int warp = threadIdx.x >> 5, lane = threadIdx.x & 31;
    int row  = blockIdx.x * 8 + warp;
    float h0 = g_h[(size_t)row * HH + lane];
    float h1 = g_h[(size_t)row * HH + lane + 32];
    float acc = bu[lane];
#pragma unroll
    for (int hh = 0; hh < HH; hh++) {
        float hv = __shfl_sync(FULLM, (hh < 32) ? h0 : h1, hh & 31);
        acc += hv * sW[hh * CC + lane];
    }
    g_unary[row * CC + lane] = acc;
#pragma unroll
    for (int k = 0; k < KK; k++) {
        float d0 = (h0 - sM[k * HH + lane])      / sS[k * HH + lane];
        float d1 = (h1 - sM[k * HH + lane + 32]) / sS[k * HH + lane + 32];
        float s = d0 * d0 + d1 * d1;
#pragma unroll
        for (int o = 16; o; o >>= 1) s += __shfl_xor_sync(FULLM, s, o);
        s = __shfl_sync(FULLM, s, 0);
        if (lane == 0) g_e[row * KK + k] = expf(-s);
    }
}

// ------------- K6: initial Q = softmax(unary) -------------------------------
__global__ void k_softmax0() {
    int warp = threadIdx.x >> 5, lane = threadIdx.x & 31;
    int row  = blockIdx.x * 8 + warp;
    float v = g_unary[row * CC + lane];
    float m = v;
#pragma unroll
    for (int o = 16; o; o >>= 1) m = fmaxf(m, __shfl_xor_sync(FULLM, m, o));
    float ex = expf(v - m);
    float s = ex;
#pragma unroll
    for (int o = 16; o; o >>= 1) s += __shfl_xor_sync(FULLM, s, o);
    g_Q[row * CC + lane] = ex / s;
}

// ------------- CRF iter part 1: Y[j] = e[j][k] * (Q@mu)[j][c] ---------------
__global__ void k_Y(const float* __restrict__ mu) {
    __shared__ float sMu[CC * CC];
    for (int i = threadIdx.x; i < CC * CC; i += 256) sMu[i] = mu[i];
    __syncthreads();
    int warp = threadIdx.x >> 5, lane = threadIdx.x & 31;
    int row  = blockIdx.x * 8 + warp;
    float q = g_Q[row * CC + lane];
    float p = 0.f;
#pragma unroll
    for (int c = 0; c < CC; c++) p += __shfl_sync(FULLM, q, c) * sMu[c * CC + lane];
    float e0 = g_e[row * KK], e1 = g_e[row * KK + 1];
    g_Y[(size_t)row * 64 + lane]      = e0 * p;
    g_Y[(size_t)row * 64 + 32 + lane] = e1 * p;
}

// ------------- CRF iter part 2: per-batch column sums of Y ------------------
__global__ void k_cs() {
    __shared__ float s[256];
    int b = blockIdx.x, t = threadIdx.x;
    const float* Yb = g_Y + (size_t)b * NN * 64;
    float a = 0.f;
    for (int base = t; base < NN * 64; base += 256) a += Yb[base];   // col = t&63 fixed
    s[t] = a; __syncthreads();
    if (t < 64) g_cs[b * 64 + t] = s[t] + s[t + 64] + s[t + 128] + s[t + 192];
}

// ------------- CRF iter part 3: msg via complement trick + softmax ----------
__global__ void k_msg(const float* __restrict__ kw) {
    int warp = threadIdx.x >> 5, lane = threadIdx.x & 31;
    int row  = blockIdx.x * 8 + warp;
    int b    = row >> 10;
    int base = b << 10;
    float z0 = g_cs[b * 64 + lane], z1 = g_cs[b * 64 + 32 + lane];
    unsigned myz = ~g_adjl[row * 32 + lane];           // zero-mask (usually 0)
    if (__any_sync(FULLM, myz != 0u)) {
        for (int wk = 0; wk < 32; wk++) {
            unsigned bits = __shfl_sync(FULLM, myz, wk);
            while (bits) {
                int t = __ffs(bits) - 1; bits &= bits - 1;
                const float* Yk = g_Y + (size_t)(base + (wk << 5) + t) * 64;
                z0 -= Yk[lane]; z1 -= Yk[32 + lane];
            }
        }
    }
    float e0 = g_e[row * KK] * kw[0], e1 = g_e[row * KK + 1] * kw[1];
    float logit = (g_unary[row * CC + lane] + e0 * z0 + e1 * z1) * INV_TEMP;
    float m = logit;
#pragma unroll
    for (int o = 16; o; o >>= 1) m = fmaxf(m, __shfl_xor_sync(FULLM, m, o));
    float ex = expf(logit - m);
    float s = ex;
#pragma unroll
    for (int o = 16; o; o >>= 1) s += __shfl_xor_sync(FULLM, s, o);
    g_Q[row * CC + lane] = ex / s;
}

// ------------- K7: AQ = adj @ Q (bitset gather) -----------------------------
__global__ void k_AQ() {
    extern __shared__ float sQ[];                  // NN x 32
    int b = blockIdx.x, chunk = blockIdx.y;
    const float* Qb = g_Q + (size_t)b * NN * CC;
    for (int idx = threadIdx.x; idx < NN * CC; idx += blockDim.x) sQ[idx] = Qb[idx];
    __syncthreads();
    int warp = threadIdx.x >> 5, lane = threadIdx.x & 31;
    for (int r = warp; r < 128; r += 16) {
        int i   = chunk * 128 + r;
        int row = b * NN + i;
        unsigned myw = g_adjb[row * 32 + lane];
        const float* sl = sQ + lane;
        float acc = 0.f;
        for (int wk = 0; wk < 32; wk++) {
            unsigned bits = __shfl_sync(FULLM, myw, wk);
            int bse = wk << 5;
            while (bits) {
                int t = __ffs(bits) - 1; bits &= bits - 1;
                acc += sl[(bse + t) << 5];
            }
        }
        g_AQ[(size_t)row * CC + lane] = acc;
    }
}

// ------------- K8: pooled outputs -------------------------------------------
__global__ void k_pool(float* __restrict__ out) {
    int b = blockIdx.x, c = blockIdx.y, t = threadIdx.x;   // t in [0,64)
    const float* Qc  = g_Q  + (size_t)b * NN * CC + c;
    const float* hb  = g_h  + (size_t)b * NN * HH;
    const float* aqb = g_AQ + (size_t)b * NN * CC;
    float accx = 0.f, acca = 0.f;
    for (int n = 0; n < NN; n++) {
        float q = Qc[(size_t)n * CC];
        accx += q * hb[(size_t)n * HH + t];
        if (t < CC) acca += q * aqb[(size_t)n * CC + t];
    }
    out[((size_t)b * CC + c) * HH + t] = accx;                                   // x_pooled
    if (t < CC)
        out[(size_t)BB * CC * HH + ((size_t)b * CC + c) * CC + t] = acca;        // adj_pooled
}

// ---------------------------------------------------------------------------
extern "C" void kernel_launch(void* const* d_in, const int* in_sizes, int n_in,
                              void* d_out, int out_size) {
    const float* x      = (const float*)d_in[0];
    const int*   adj    = (const int*)  d_in[1];
    const float* Wg     = (const float*)d_in[2];
    const float* bg     = (const float*)d_in[3];
    const float* Wu     = (const float*)d_in[4];
    const float* bu     = (const float*)d_in[5];
    const float* means  = (const float*)d_in[6];
    const float* scales = (const float*)d_in[7];
    const float* kw     = (const float*)d_in[8];
    const float* mu     = (const float*)d_in[9];
    float* out = (float*)d_out;

    cudaFuncSetAttribute(k_gcnagg, cudaFuncAttributeMaxDynamicSharedMemorySize, NN * 32 * 4);
    cudaFuncSetAttribute(k_AQ,     cudaFuncAttributeMaxDynamicSharedMemorySize, NN * 32 * 4);

    k_bits    <<<ROWS / 8,  256>>>(adj);
    k_xw      <<<ROWS / 32, 256>>>(x, Wg);
    k_adjl    <<<ROWS / 8,  256>>>();
    k_gcnagg  <<<dim3(BB, 2, 8), 512, NN * 32 * 4>>>(bg);
    k_unary_e <<<ROWS / 8,  256>>>(Wu, bu, means, scales);
    k_softmax0<<<ROWS / 8,  256>>>();
    for (int it = 0; it < NITER; it++) {
        k_Y   <<<ROWS / 8, 256>>>(mu);
        k_cs  <<<BB,       256>>>();
        k_msg <<<ROWS / 8, 256>>>(kw);
    }
    k_AQ   <<<dim3(BB, 8), 512, NN * 32 * 4>>>();
    k_pool <<<dim3(BB, CC), 64>>>(out);
}

// round 3
// speedup vs baseline: 2.5668x; 2.5668x over previous
#include <cuda_runtime.h>

#define BB 32
#define NN 1024
#define FF 128
#define HH 64
#define CC 32
#define KK 2
#define NITER 5
#define INV_TEMP 2.0f
#define ROWS (BB*NN)
#define FULLM 0xffffffffu

typedef unsigned long long u64;

// packed fp32x2 FMA (2x fp32 throughput on sm_103a; ptxas never auto-emits)
#define FMA2(acc, a, b) asm("fma.rn.f32x2 %0, %1, %2, %0;" : "+l"(acc) : "l"(a), "l"(b))
__device__ __forceinline__ u64 pack2(float lo, float hi) {
    u64 r;
    asm("mov.b64 %0, {%1,%2};" : "=l"(r) : "r"(__float_as_uint(lo)), "r"(__float_as_uint(hi)));
    return r;
}
__device__ __forceinline__ void unpack2(u64 v, float& lo, float& hi) {
    unsigned a, b;
    asm("mov.b64 {%0,%1}, %2;" : "=r"(a), "=r"(b) : "l"(v));
    lo = __uint_as_float(a); hi = __uint_as_float(b);
}

// ---------------- scratch (device globals; allocation-free) ----------------
__device__ float    g_dY[ROWS*HH];     // dinv_j * (x @ W_gcn)[j,:]
__device__ float    g_dinv[ROWS];
__device__ unsigned g_adjb[ROWS*32];   // bit-packed adjacency rows
__device__ unsigned g_adjl[ROWS*32];   // bit-packed 2-hop reachability
__device__ float    g_h[ROWS*HH];
__device__ float    g_unary[ROWS*CC];
__device__ float    g_e[ROWS*KK];
__device__ float    g_Q[ROWS*CC];
__device__ float    g_Y[ROWS*64];      // Y[j][k*32+c] = e[j][k] * (Q@mu)[j][c]
__device__ float    g_csp[(ROWS/8)*64];// per-block partial colsums of Y
__device__ float    g_cs[BB*64];       // per-batch column sums of Y
__device__ float    g_AQ[ROWS*CC];     // adj @ Q
__device__ float    g_poolp[(size_t)BB*16*3072]; // pooling partials

// ------------- K1: pack adjacency bits + degree -> dinv ---------------------
__global__ void k_bits(const int* __restrict__ adj) {
    int warp = threadIdx.x >> 5, lane = threadIdx.x & 31;
    int row  = blockIdx.x * 8 + warp;
    const int* ar = adj + (size_t)row * NN;
    unsigned myw = 0;
#pragma unroll
    for (int w = 0; w < 32; w++) {
        unsigned bal = __ballot_sync(FULLM, ar[(w << 5) + lane] != 0);
        if (lane == w) myw = bal;
    }
    g_adjb[row * 32 + lane] = myw;
    int d = __popc(myw);
#pragma unroll
    for (int o = 16; o; o >>= 1) d += __shfl_xor_sync(FULLM, d, o);
    if (lane == 0) g_dinv[row] = rsqrtf((float)d + 1.0f);   // +1 self loop
}

// ------------- K2: xw = x @ W_gcn, scaled by dinv ---------------------------
__global__ void k_xw(const float* __restrict__ x, const float* __restrict__ Wg) {
    __shared__ float Ws[FF * HH];
    for (int i = threadIdx.x; i < FF * HH; i += 256) Ws[i] = Wg[i];
    __syncthreads();
    int warp = threadIdx.x >> 5, lane = threadIdx.x & 31;
    for (int r = 0; r < 4; r++) {
        int row = blockIdx.x * 32 + warp * 4 + r;
        const float* xr = x + (size_t)row * FF;
        float a0 = 0.f, a1 = 0.f;
        for (int kb = 0; kb < FF; kb += 32) {
            float xv32 = xr[kb + lane];
#pragma unroll
            for (int t = 0; t < 32; t++) {
                float xv = __shfl_sync(FULLM, xv32, t);
                a0 += xv * Ws[(kb + t) * HH + lane];
                a1 += xv * Ws[(kb + t) * HH + lane + 32];
            }
        }
        float di = g_dinv[row];
        g_dY[(size_t)row * HH + lane]      = a0 * di;
        g_dY[(size_t)row * HH + lane + 32] = a1 * di;
    }
}

// ------------- K3: 2-hop reachability bitsets (OR of neighbor rows) ---------
__global__ void k_adjl() {
    int warp = threadIdx.x >> 5, lane = threadIdx.x & 31;
    int row  = blockIdx.x * 8 + warp;
    int base = (row >> 10) << 10;                 // batch start row
    unsigned myw = g_adjb[row * 32 + lane];
    unsigned acc = 0;
    for (int wk = 0; wk < 32; wk++) {
        unsigned bits = __shfl_sync(FULLM, myw, wk);
        while (bits) {
            int t = __ffs(bits) - 1; bits &= bits - 1;
            acc |= g_adjb[(size_t)(base + (wk << 5) + t) * 32 + lane];
        }
        if (__all_sync(FULLM, acc == FULLM)) break;   // saturated -> done
    }
    g_adjl[row * 32 + lane] = acc;
}

// ------------- K4: dense GCN aggregate via fp32x2 register-tiled GEMM -------
// C[128x64] = A(bits)[128x1024] @ dY[1024x64]; h = relu(dinv_i*(C + dY_i) + b)
__global__ void k_gcnagg_dense(const float* __restrict__ bg) {
    __shared__ float As[64 * 128];   // 32KB : A chunk transposed [k][r]
    __shared__ float Bs[64 * 64];    // 16KB : dY chunk [k][c]
    int b = blockIdx.y, chunk = blockIdx.x;
    int tid = threadIdx.x;
    int tx = tid & 15, ty = tid >> 4;         // tx: col grp of 4, ty: row grp of 8
    int rowbase = b * NN + chunk * 128;
    u64 acc[4][4];
#pragma unroll
    for (int i = 0; i < 4; i++)
#pragma unroll
        for (int j = 0; j < 4; j++) acc[i][j] = 0ull;

    int er = tid >> 1, ew = tid & 1;
    const unsigned* abase = g_adjb + (size_t)rowbase * 32;

    for (int kc = 0; kc < 16; kc++) {
        __syncthreads();
        // expand 128 rows x 64 bits of A into float smem (transposed)
        unsigned word = abase[(size_t)er * 32 + kc * 2 + ew];
#pragma unroll
        for (int bit = 0; bit < 32; bit++)
            As[(ew * 32 + bit) * 128 + er] = ((word >> bit) & 1) ? 1.0f : 0.0f;
        // stage B chunk: dY rows [kc*64, kc*64+64), all 64 cols
        const float4* src = (const float4*)(g_dY + (size_t)(b * NN + kc * 64) * HH);
        float4* dst = (float4*)Bs;
#pragma unroll
        for (int q = 0; q < 4; q++) dst[tid + q * 256] = src[tid + q * 256];
        __syncthreads();

#pragma unroll 4
        for (int k = 0; k < 64; k++) {
            float4 al = *(const float4*)&As[k * 128 + ty * 8];
            float4 ah = *(const float4*)&As[k * 128 + ty * 8 + 4];
            float4 bq = *(const float4*)&Bs[k * 64 + tx * 4];
            u64 ap[4] = { pack2(al.x, al.y), pack2(al.z, al.w),
                          pack2(ah.x, ah.y), pack2(ah.z, ah.w) };
            u64 bp[4] = { pack2(bq.x, bq.x), pack2(bq.y, bq.y),
                          pack2(bq.z, bq.z), pack2(bq.w, bq.w) };
#pragma unroll
            for (int rp = 0; rp < 4; rp++)
#pragma unroll
                for (int c = 0; c < 4; c++)
                    FMA2(acc[rp][c], ap[rp], bp[c]);
        }
    }

    float4 bias = *(const float4*)&bg[tx * 4];
#pragma unroll
    for (int rp = 0; rp < 4; rp++) {
        int r0 = rowbase + ty * 8 + rp * 2;
        float4 s0 = *(const float4*)&g_dY[(size_t)r0 * HH + tx * 4];
        float4 s1 = *(const float4*)&g_dY[(size_t)(r0 + 1) * HH + tx * 4];
        float d0 = g_dinv[r0], d1 = g_dinv[r0 + 1];
        float o0[4], o1[4];
#pragma unroll
        for (int c = 0; c < 4; c++) unpack2(acc[rp][c], o0[c], o1[c]);
        float4 h0, h1;
        h0.x = fmaxf(fmaf(o0[0] + s0.x, d0, bias.x), 0.f);
        h0.y = fmaxf(fmaf(o0[1] + s0.y, d0, bias.y), 0.f);
        h0.z = fmaxf(fmaf(o0[2] + s0.z, d0, bias.z), 0.f);
        h0.w = fmaxf(fmaf(o0[3] + s0.w, d0, bias.w), 0.f);
        h1.x = fmaxf(fmaf(o1[0] + s1.x, d1, bias.x), 0.f);
        h1.y = fmaxf(fmaf(o1[1] + s1.y, d1, bias.y), 0.f);
        h1.z = fmaxf(fmaf(o1[2] + s1.z, d1, bias.z), 0.f);
        h1.w = fmaxf(fmaf(o1[3] + s1.w, d1, bias.w), 0.f);
        *(float4*)&g_h[(size_t)r0 * HH + tx * 4]       = h0;
        *(float4*)&g_h[(size_t)(r0 + 1) * HH + tx * 4] = h1;
    }
}

// ------------- K5: unary = h @ W_unary + b; e; fused softmax -> Q -----------
__global__ void k_unary_e(const float* __restrict__ Wu, const float* __restrict__ bu,
                          const float* __restrict__ means, const float* __restrict__ scales) {
    __shared__ float sW[HH * CC];
    __shared__ float sM[KK * HH], sS[KK * HH];
    for (int i = threadIdx.x; i < HH * CC; i += 256) sW[i] = Wu[i];
    for (int i = threadIdx.x; i < KK * HH; i += 256) { sM[i] = means[i]; sS[i] = scales[i]; }
    __syncthreads();
    int warp = threadIdx.x >> 5, lane = threadIdx.x & 31;
    int row  = blockIdx.x * 8 + warp;
    float h0 = g_h[(size_t)row * HH + lane];
    float h1 = g_h[(size_t)row * HH + lane + 32];
    float acc = bu[lane];
#pragma unroll
    for (int hh = 0; hh < HH; hh++) {
        float hv = __shfl_sync(FULLM, (hh < 32) ? h0 : h1, hh & 31);
        acc += hv * sW[hh * CC + lane];
    }
    g_unary[row * CC + lane] = acc;
#pragma unroll
    for (int k = 0; k < KK; k++) {
        float d0 = (h0 - sM[k * HH + lane])      / sS[k * HH + lane];
        float d1 = (h1 - sM[k * HH + lane + 32]) / sS[k * HH + lane + 32];
        float s = d0 * d0 + d1 * d1;
#pragma unroll
        for (int o = 16; o; o >>= 1) s += __shfl_xor_sync(FULLM, s, o);
        s = __shfl_sync(FULLM, s, 0);
        if (lane == 0) g_e[row * KK + k] = expf(-s);
    }
    // fused initial softmax: Q = softmax(unary)
    float m = acc;
#pragma unroll
    for (int o = 16; o; o >>= 1) m = fmaxf(m, __shfl_xor_sync(FULLM, m, o));
    float ex = expf(acc - m);
    float s = ex;
#pragma unroll
    for (int o = 16; o; o >>= 1) s += __shfl_xor_sync(FULLM, s, o);
    g_Q[row * CC + lane] = ex / s;
}

// ------------- CRF part 1: Y + per-block partial colsums --------------------
__global__ void k_Y(const float* __restrict__ mu) {
    __shared__ float sMu[CC * CC];
    __shared__ float sp[8][64];
    for (int i = threadIdx.x; i < CC * CC; i += 256) sMu[i] = mu[i];
    __syncthreads();
    int warp = threadIdx.x >> 5, lane = threadIdx.x & 31;
    int row  = blockIdx.x * 8 + warp;
    float q = g_Q[row * CC + lane];
    float p = 0.f;
#pragma unroll
    for (int c = 0; c < CC; c++) p += __shfl_sync(FULLM, q, c) * sMu[c * CC + lane];
    float e0 = g_e[row * KK], e1 = g_e[row * KK + 1];
    float y0 = e0 * p, y1 = e1 * p;
    g_Y[(size_t)row * 64 + lane]      = y0;
    g_Y[(size_t)row * 64 + 32 + lane] = y1;
    sp[warp][lane]      = y0;
    sp[warp][32 + lane] = y1;
    __syncthreads();
    int t = threadIdx.x;
    if (t < 64) {
        float s = 0.f;
#pragma unroll
        for (int w = 0; w < 8; w++) s += sp[w][t];
        g_csp[blockIdx.x * 64 + t] = s;
    }
}

// ------------- CRF part 2: reduce partials to per-batch colsums -------------
__global__ void k_cs() {
    int b = blockIdx.x, t = threadIdx.x;   // 64 threads
    float s = 0.f;
    for (int i = 0; i < 128; i++) s += g_csp[(b * 128 + i) * 64 + t];
    g_cs[b * 64 + t] = s;
}

// ------------- CRF part 3: msg via complement trick + softmax ---------------
__global__ void k_msg(const float* __restrict__ kw) {
    int warp = threadIdx.x >> 5, lane = threadIdx.x & 31;
    int row  = blockIdx.x * 8 + warp;
    int b    = row >> 10;
    int base = b << 10;
    float z0 = g_cs[b * 64 + lane], z1 = g_cs[b * 64 + 32 + lane];
    unsigned myz = ~g_adjl[row * 32 + lane];           // zero-mask (usually 0)
    if (__any_sync(FULLM, myz != 0u)) {
        for (int wk = 0; wk < 32; wk++) {
            unsigned bits = __shfl_sync(FULLM, myz, wk);
            while (bits) {
                int t = __ffs(bits) - 1; bits &= bits - 1;
                const float* Yk = g_Y + (size_t)(base + (wk << 5) + t) * 64;
                z0 -= Yk[lane]; z1 -= Yk[32 + lane];
            }
        }
    }
    float e0 = g_e[row * KK] * kw[0], e1 = g_e[row * KK + 1] * kw[1];
    float logit = (g_unary[row * CC + lane] + e0 * z0 + e1 * z1) * INV_TEMP;
    float m = logit;
#pragma unroll
    for (int o = 16; o; o >>= 1) m = fmaxf(m, __shfl_xor_sync(FULLM, m, o));
    float ex = expf(logit - m);
    float s = ex;
#pragma unroll
    for (int o = 16; o; o >>= 1) s += __shfl_xor_sync(FULLM, s, o);
    g_Q[row * CC + lane] = ex / s;
}

// ------------- K7: AQ = adj @ Q, dense fp32x2 GEMM --------------------------
__global__ void k_AQ_dense() {
    __shared__ float As[64 * 128];   // 32KB
    __shared__ float Qs[64 * 32];    // 8KB
    int b = blockIdx.y, chunk = blockIdx.x;
    int tid = threadIdx.x;
    int tx = tid & 7, ty = tid >> 3;          // tx: col grp of 4 (32 cols), ty: row grp of 4
    int rowbase = b * NN + chunk * 128;
    u64 acc[2][4];
#pragma unroll
    for (int i = 0; i < 2; i++)
#pragma unroll
        for (int j = 0; j < 4; j++) acc[i][j] = 0ull;

    int er = tid >> 1, ew = tid & 1;
    const unsigned* abase = g_adjb + (size_t)rowbase * 32;

    for (int kc = 0; kc < 16; kc++) {
        __syncthreads();
        unsigned word = abase[(size_t)er * 32 + kc * 2 + ew];
#pragma unroll
        for (int bit = 0; bit < 32; bit++)
            As[(ew * 32 + bit) * 128 + er] = ((word >> bit) & 1) ? 1.0f : 0.0f;
        const float4* src = (const float4*)(g_Q + (size_t)(b * NN + kc * 64) * CC);
        float4* dst = (float4*)Qs;
        dst[tid]       = src[tid];
        dst[tid + 256] = src[tid + 256];
        __syncthreads();

#pragma unroll 4
        for (int k = 0; k < 64; k++) {
            float4 a = *(const float4*)&As[k * 128 + ty * 4];
            float4 q = *(const float4*)&Qs[k * 32 + tx * 4];
            u64 ap[2] = { pack2(a.x, a.y), pack2(a.z, a.w) };
            u64 qp[4] = { pack2(q.x, q.x), pack2(q.y, q.y),
                          pack2(q.z, q.z), pack2(q.w, q.w) };
#pragma unroll
            for (int rp = 0; rp < 2; rp++)
#pragma unroll
                for (int c = 0; c < 4; c++)
                    FMA2(acc[rp][c], ap[rp], qp[c]);
        }
    }

#pragma unroll
    for (int rp = 0; rp < 2; rp++) {
        int r0 = rowbase + ty * 4 + rp * 2;
        float o0[4], o1[4];
#pragma unroll
        for (int c = 0; c < 4; c++) unpack2(acc[rp][c], o0[c], o1[c]);
        *(float4*)&g_AQ[(size_t)r0 * CC + tx * 4]       = make_float4(o0[0], o0[1], o0[2], o0[3]);
        *(float4*)&g_AQ[(size_t)(r0 + 1) * CC + tx * 4] = make_float4(o1[0], o1[1], o1[2], o1[3]);
    }
}

// ------------- K8a: pooled outputs, N-split partials ------------------------
__global__ void k_poolp() {
    __shared__ float Qs[64 * 32];    // 8KB
    __shared__ float hs[64 * 64];    // 16KB
    __shared__ float Aq[64 * 32];    // 8KB
    int b = blockIdx.x, nc = blockIdx.y;   // 16 chunks of 64 nodes
    int tid = threadIdx.x;                  // 256
    int n0 = b * NN + nc * 64;
    {
        const float4* sq = (const float4*)(g_Q  + (size_t)n0 * CC);
        const float4* sh = (const float4*)(g_h  + (size_t)n0 * HH);
        const float4* sa = (const float4*)(g_AQ + (size_t)n0 * CC);
        ((float4*)Qs)[tid] = sq[tid];  ((float4*)Qs)[tid + 256] = sq[tid + 256];
        ((float4*)Aq)[tid] = sa[tid];  ((float4*)Aq)[tid + 256] = sa[tid + 256];
#pragma unroll
        for (int q = 0; q < 4; q++) ((float4*)hs)[tid + q * 256] = sh[tid + q * 256];
    }
    __syncthreads();
    int tx = tid & 15, ty = tid >> 4;   // ty: c grp of 2; tx: hcol grp of 4 / acol grp of 2
    float xp[2][4] = {};
    float ap[2][2] = {};
    for (int n = 0; n < 64; n++) {
        float q0 = Qs[n * 32 + ty * 2], q1 = Qs[n * 32 + ty * 2 + 1];
        float4 hv = *(const float4*)&hs[n * 64 + tx * 4];
        float a0 = Aq[n * 32 + tx * 2], a1 = Aq[n * 32 + tx * 2 + 1];
        xp[0][0] += q0 * hv.x; xp[0][1] += q0 * hv.y; xp[0][2] += q0 * hv.z; xp[0][3] += q0 * hv.w;
        xp[1][0] += q1 * hv.x; xp[1][1] += q1 * hv.y; xp[1][2] += q1 * hv.z; xp[1][3] += q1 * hv.w;
        ap[0][0] += q0 * a0; ap[0][1] += q0 * a1;
        ap[1][0] += q1 * a0; ap[1][1] += q1 * a1;
    }
    float* dst = g_poolp + ((size_t)b * 16 + nc) * 3072;
#pragma unroll
    for (int cc = 0; cc < 2; cc++) {
#pragma unroll
        for (int c4 = 0; c4 < 4; c4++)
            dst[(ty * 2 + cc) * 64 + tx * 4 + c4] = xp[cc][c4];
#pragma unroll
        for (int a = 0; a < 2; a++)
            dst[2048 + (ty * 2 + cc) * 32 + tx * 2 + a] = ap[cc][a];
    }
}

// ------------- K8b: reduce pooling partials to output -----------------------
__global__ void k_poolred(float* __restrict__ out) {
    int b = blockIdx.x;
    int idx = blockIdx.y * 256 + threadIdx.x;   // 12*256 = 3072
    float s = 0.f;
    for (int ch = 0; ch < 16; ch++) s += g_poolp[((size_t)b * 16 + ch) * 3072 + idx];
    if (idx < 2048) {
        int c = idx >> 6, hcol = idx & 63;
        out[((size_t)b * CC + c) * HH + hcol] = s;                                 // x_pooled
    } else {
        int j = idx - 2048, c = j >> 5, a = j & 31;
        out[(size_t)BB * CC * HH + ((size_t)b * CC + c) * CC + a] = s;             // adj_pooled
    }
}

// ---------------------------------------------------------------------------
extern "C" void kernel_launch(void* const* d_in, const int* in_sizes, int n_in,
                              void* d_out, int out_size) {
    const float* x      = (const float*)d_in[0];
    const int*   adj    = (const int*)  d_in[1];
    const float* Wg     = (const float*)d_in[2];
    const float* bg     = (const float*)d_in[3];
    const float* Wu     = (const float*)d_in[4];
    const float* bu     = (const float*)d_in[5];
    const float* means  = (const float*)d_in[6];
    const float* scales = (const float*)d_in[7];
    const float* kw     = (const float*)d_in[8];
    const float* mu     = (const float*)d_in[9];
    float* out = (float*)d_out;

    k_bits        <<<ROWS / 8,  256>>>(adj);
    k_xw          <<<ROWS / 32, 256>>>(x, Wg);
    k_adjl        <<<ROWS / 8,  256>>>();
    k_gcnagg_dense<<<dim3(8, BB), 256>>>(bg);
    k_unary_e     <<<ROWS / 8,  256>>>(Wu, bu, means, scales);
    for (int it = 0; it < NITER; it++) {
        k_Y   <<<ROWS / 8, 256>>>(mu);
        k_cs  <<<BB,       64>>>();
        k_msg <<<ROWS / 8, 256>>>(kw);
    }
    k_AQ_dense <<<dim3(8, BB), 256>>>();
    k_poolp    <<<dim3(BB, 16), 256>>>();
    k_poolred  <<<dim3(BB, 12), 256>>>(out);
}

// round 5
// speedup vs baseline: 3.6979x; 1.4407x over previous
#include <cuda_runtime.h>

#define BB 32
#define NN 1024
#define FF 128
#define HH 64
#define CC 32
#define KK 2
#define NITER 5
#define INV_TEMP 2.0f
#define ROWS (BB*NN)
#define FULLM 0xffffffffu
#define KC 64

// padded duplicated-B strides (bank-conflict-free across tx)
#define BSTRIDE_G 160   // gcnagg: 8 tx slots * 20 words
#define BSLOT_G   20
#define BSTRIDE_A 96    // AQ: 8 tx slots * 12 words
#define BSLOT_A   12

typedef unsigned long long u64;

// packed fp32x2 FMA (2x fp32 throughput on sm_103a; ptxas never auto-emits)
#define FMA2(acc, a, b) asm("fma.rn.f32x2 %0, %1, %2, %0;" : "+l"(acc) : "l"(a), "l"(b))
__device__ __forceinline__ u64 pack2(float lo, float hi) {
    u64 r;
    asm("mov.b64 %0, {%1,%2};" : "=l"(r) : "r"(__float_as_uint(lo)), "r"(__float_as_uint(hi)));
    return r;
}
__device__ __forceinline__ void unpack2(u64 v, float& lo, float& hi) {
    unsigned a, b;
    asm("mov.b64 {%0,%1}, %2;" : "=r"(a), "=r"(b) : "l"(v));
    lo = __uint_as_float(a); hi = __uint_as_float(b);
}

// ---------------- scratch (device globals; allocation-free) ----------------
__device__ float    g_dY[ROWS*HH];
__device__ float    g_dinv[ROWS];
__device__ unsigned g_adjb[ROWS*32];
__device__ unsigned g_adjl[ROWS*32];
__device__ float    g_h[ROWS*HH];
__device__ float    g_unary[ROWS*CC];
__device__ float    g_e[ROWS*KK];
__device__ float    g_Qa[ROWS*CC];
__device__ float    g_Qb[ROWS*CC];
__device__ float    g_csp[(ROWS/8)*64];
__device__ float    g_cs[BB*64];
__device__ float    g_AQ[ROWS*CC];
__device__ float    g_poolp[(size_t)BB*16*3072];

__device__ __forceinline__ const float* qsel(int s) { return s ? g_Qb : g_Qa; }
__device__ __forceinline__ float*       qselw(int s){ return s ? g_Qb : g_Qa; }

// ------------- K1: pack adjacency bits + degree -> dinv ---------------------
__global__ void k_bits(const int* __restrict__ adj) {
    int warp = threadIdx.x >> 5, lane = threadIdx.x & 31;
    int row  = blockIdx.x * 8 + warp;
    const int* ar = adj + (size_t)row * NN;
    unsigned myw = 0;
#pragma unroll
    for (int w = 0; w < 32; w++) {
        unsigned bal = __ballot_sync(FULLM, ar[(w << 5) + lane] != 0);
        if (lane == w) myw = bal;
    }
    g_adjb[row * 32 + lane] = myw;
    int d = __popc(myw);
#pragma unroll
    for (int o = 16; o; o >>= 1) d += __shfl_xor_sync(FULLM, d, o);
    if (lane == 0) g_dinv[row] = rsqrtf((float)d + 1.0f);
}

// ------------- K2: xw = x @ W_gcn, scaled by dinv ---------------------------
__global__ void k_xw(const float* __restrict__ x, const float* __restrict__ Wg) {
    __shared__ float Ws[FF * HH];
    for (int i = threadIdx.x; i < FF * HH; i += 256) Ws[i] = Wg[i];
    __syncthreads();
    int warp = threadIdx.x >> 5, lane = threadIdx.x & 31;
    for (int r = 0; r < 4; r++) {
        int row = blockIdx.x * 32 + warp * 4 + r;
        const float* xr = x + (size_t)row * FF;
        float a0 = 0.f, a1 = 0.f;
        for (int kb = 0; kb < FF; kb += 32) {
            float xv32 = xr[kb + lane];
#pragma unroll
            for (int t = 0; t < 32; t++) {
                float xv = __shfl_sync(FULLM, xv32, t);
                a0 += xv * Ws[(kb + t) * HH + lane];
                a1 += xv * Ws[(kb + t) * HH + lane + 32];
            }
        }
        float di = g_dinv[row];
        g_dY[(size_t)row * HH + lane]      = a0 * di;
        g_dY[(size_t)row * HH + lane + 32] = a1 * di;
    }
}

// ------------- K3: 2-hop reachability bitsets -------------------------------
__global__ void k_adjl() {
    int warp = threadIdx.x >> 5, lane = threadIdx.x & 31;
    int row  = blockIdx.x * 8 + warp;
    int base = (row >> 10) << 10;
    unsigned myw = g_adjb[row * 32 + lane];
    unsigned acc = 0;
    for (int wk = 0; wk < 32; wk++) {
        unsigned bits = __shfl_sync(FULLM, myw, wk);
        while (bits) {
            int t = __ffs(bits) - 1; bits &= bits - 1;
            acc |= g_adjb[(size_t)(base + (wk << 5) + t) * 32 + lane];
        }
        if (__all_sync(FULLM, acc == FULLM)) break;
    }
    g_adjl[row * 32 + lane] = acc;
}

// ------------- K4: GCN aggregate, 256x64 tile, 8x8/thread fp32x2 ------------
__global__ void __launch_bounds__(256, 1) k_gcnagg_dense(const float* __restrict__ bg) {
    extern __shared__ float sm[];
    float* As  = sm;                      // [KC][256]
    float* Bs2 = sm + KC * 256;           // [KC][BSTRIDE_G] duplicated, padded
    int b = blockIdx.y, chunk = blockIdx.x;
    int tid = threadIdx.x;
    int tx = tid & 7, ty = tid >> 3;      // tx: 8 cols, ty: 8 rows
    int rowbase = b * NN + chunk * 256;
    u64 acc[4][8];
#pragma unroll
    for (int i = 0; i < 4; i++)
#pragma unroll
        for (int j = 0; j < 8; j++) acc[i][j] = 0ull;

    const unsigned* abase = g_adjb + (size_t)rowbase * 32;

    for (int kc = 0; kc < 16; kc++) {
        __syncthreads();
        // expand A bits: thread t handles tile-row t, 64 k-bits
        unsigned w0 = abase[(size_t)tid * 32 + kc * 2];
        unsigned w1 = abase[(size_t)tid * 32 + kc * 2 + 1];
#pragma unroll
        for (int bit = 0; bit < 32; bit++) {
            As[bit * 256 + tid]        = (float)((w0 >> bit) & 1);
            As[(32 + bit) * 256 + tid] = (float)((w1 >> bit) & 1);
        }
        // stage B (dY rows kc*64..+64, 64 cols) duplicated (b,b), padded slots
        {
            const float4* src = (const float4*)(g_dY + (size_t)(b * NN + kc * 64) * HH);
#pragma unroll
            for (int q = 0; q < 4; q++) {
                int j = tid + q * 256;               // 1024 float4s
                float4 v = src[j];
                int r = j >> 4, c4 = (j & 15) * 4;   // cols c4..c4+3 (same 8-group)
                int g = c4 >> 3, wc = c4 & 7;
                float* dst = &Bs2[r * BSTRIDE_G + g * BSLOT_G + wc * 2];
                *(float4*)(dst)     = make_float4(v.x, v.x, v.y, v.y);
                *(float4*)(dst + 4) = make_float4(v.z, v.z, v.w, v.w);
            }
        }
        __syncthreads();

#pragma unroll 4
        for (int k = 0; k < KC; k++) {
            float4 a0 = *(const float4*)&As[k * 256 + ty * 8];
            float4 a1 = *(const float4*)&As[k * 256 + ty * 8 + 4];
            u64 ap[4] = { pack2(a0.x, a0.y), pack2(a0.z, a0.w),
                          pack2(a1.x, a1.y), pack2(a1.z, a1.w) };
            const float* bp = &Bs2[k * BSTRIDE_G + tx * BSLOT_G];
            float4 b0 = *(const float4*)(bp);
            float4 b1 = *(const float4*)(bp + 4);
            float4 b2 = *(const float4*)(bp + 8);
            float4 b3 = *(const float4*)(bp + 12);
            u64 bq[8] = { pack2(b0.x, b0.y), pack2(b0.z, b0.w),
                          pack2(b1.x, b1.y), pack2(b1.z, b1.w),
                          pack2(b2.x, b2.y), pack2(b2.z, b2.w),
                          pack2(b3.x, b3.y), pack2(b3.z, b3.w) };
#pragma unroll
            for (int rp = 0; rp < 4; rp++)
#pragma unroll
                for (int c = 0; c < 8; c++)
                    FMA2(acc[rp][c], ap[rp], bq[c]);
        }
    }

    // epilogue: h = relu(dinv_i*(C + dY_i) + bias)
    float4 bl = *(const float4*)&bg[tx * 8];
    float4 bh = *(const float4*)&bg[tx * 8 + 4];
#pragma unroll
    for (int rp = 0; rp < 4; rp++) {
        int r0 = rowbase + ty * 8 + rp * 2;
#pragma unroll
        for (int rr = 0; rr < 2; rr++) {
            int r = r0 + rr;
            float4 s0 = *(const float4*)&g_dY[(size_t)r * HH + tx * 8];
            float4 s1 = *(const float4*)&g_dY[(size_t)r * HH + tx * 8 + 4];
            float di = g_dinv[r];
            float o[8];
#pragma unroll
            for (int c = 0; c < 8; c++) {
                float lo, hi; unpack2(acc[rp][c], lo, hi);
                o[c] = rr ? hi : lo;
            }
            float4 h0, h1;
            h0.x = fmaxf(fmaf(o[0] + s0.x, di, bl.x), 0.f);
            h0.y = fmaxf(fmaf(o[1] + s0.y, di, bl.y), 0.f);
            h0.z = fmaxf(fmaf(o[2] + s0.z, di, bl.z), 0.f);
            h0.w = fmaxf(fmaf(o[3] + s0.w, di, bl.w), 0.f);
            h1.x = fmaxf(fmaf(o[4] + s1.x, di, bh.x), 0.f);
            h1.y = fmaxf(fmaf(o[5] + s1.y, di, bh.y), 0.f);
            h1.z = fmaxf(fmaf(o[6] + s1.z, di, bh.z), 0.f);
            h1.w = fmaxf(fmaf(o[7] + s1.w, di, bh.w), 0.f);
            *(float4*)&g_h[(size_t)r * HH + tx * 8]     = h0;
            *(float4*)&g_h[(size_t)r * HH + tx * 8 + 4] = h1;
        }
    }
}

// ------------- K5: unary + e + initial softmax ------------------------------
__global__ void k_unary_e(const float* __restrict__ Wu, const float* __restrict__ bu,
                          const float* __restrict__ means, const float* __restrict__ scales) {
    __shared__ float sW[HH * CC];
    __shared__ float sM[KK * HH], sS[KK * HH];
    for (int i = threadIdx.x; i < HH * CC; i += 256) sW[i] = Wu[i];
    for (int i = threadIdx.x; i < KK * HH; i += 256) { sM[i] = means[i]; sS[i] = scales[i]; }
    __syncthreads();
    int warp = threadIdx.x >> 5, lane = threadIdx.x & 31;
    int row  = blockIdx.x * 8 + warp;
    float h0 = g_h[(size_t)row * HH + lane];
    float h1 = g_h[(size_t)row * HH + lane + 32];
    float acc = bu[lane];
#pragma unroll
    for (int hh = 0; hh < HH; hh++) {
        float hv = __shfl_sync(FULLM, (hh < 32) ? h0 : h1, hh & 31);
        acc += hv * sW[hh * CC + lane];
    }
    g_unary[row * CC + lane] = acc;
#pragma unroll
    for (int k = 0; k < KK; k++) {
        float d0 = (h0 - sM[k * HH + lane])      / sS[k * HH + lane];
        float d1 = (h1 - sM[k * HH + lane + 32]) / sS[k * HH + lane + 32];
        float s = d0 * d0 + d1 * d1;
#pragma unroll
        for (int o = 16; o; o >>= 1) s += __shfl_xor_sync(FULLM, s, o);
        s = __shfl_sync(FULLM, s, 0);
        if (lane == 0) g_e[row * KK + k] = expf(-s);
    }
    float m = acc;
#pragma unroll
    for (int o = 16; o; o >>= 1) m = fmaxf(m, __shfl_xor_sync(FULLM, m, o));
    float ex = expf(acc - m);
    float s = ex;
#pragma unroll
    for (int o = 16; o; o >>= 1) s += __shfl_xor_sync(FULLM, s, o);
    g_Qa[row * CC + lane] = ex / s;
}

// ------------- CRF part 1: partial colsums of Y (no Y store) ----------------
__global__ void k_Ycs(const float* __restrict__ mu, int sel) {
    const float* Qin = qsel(sel);
    __shared__ float sMu[CC * CC];
    __shared__ float sp[8][64];
    for (int i = threadIdx.x; i < CC * CC; i += 256) sMu[i] = mu[i];
    __syncthreads();
    int warp = threadIdx.x >> 5, lane = threadIdx.x & 31;
    int row  = blockIdx.x * 8 + warp;
    float q = Qin[row * CC + lane];
    float p = 0.f;
#pragma unroll
    for (int c = 0; c < CC; c++) p += __shfl_sync(FULLM, q, c) * sMu[c * CC + lane];
    float e0 = g_e[row * KK], e1 = g_e[row * KK + 1];
    sp[warp][lane]      = e0 * p;
    sp[warp][32 + lane] = e1 * p;
    __syncthreads();
    int t = threadIdx.x;
    if (t < 64) {
        float s = 0.f;
#pragma unroll
        for (int w = 0; w < 8; w++) s += sp[w][t];
        g_csp[blockIdx.x * 64 + t] = s;
    }
}

// ------------- CRF part 2: reduce partials ----------------------------------
__global__ void k_cs() {
    int b = blockIdx.x, t = threadIdx.x;   // 64 threads
    float s = 0.f;
    for (int i = 0; i < 128; i++) s += g_csp[(b * 128 + i) * 64 + t];
    g_cs[b * 64 + t] = s;
}

// ------------- CRF part 3: msg (complement trick, Y recomputed) + softmax ---
__global__ void k_msg(const float* __restrict__ kw, const float* __restrict__ mu, int sel) {
    const float* Qin = qsel(sel);
    float* Qout = qselw(sel ^ 1);
    int warp = threadIdx.x >> 5, lane = threadIdx.x & 31;
    int row  = blockIdx.x * 8 + warp;
    int b    = row >> 10;
    int base = b << 10;
    float z0 = g_cs[b * 64 + lane], z1 = g_cs[b * 64 + 32 + lane];
    unsigned myz = ~g_adjl[row * 32 + lane];          // usually all-zero
    if (__any_sync(FULLM, myz != 0u)) {
        for (int wk = 0; wk < 32; wk++) {
            unsigned bits = __shfl_sync(FULLM, myz, wk);
            while (bits) {
                int t = __ffs(bits) - 1; bits &= bits - 1;
                int j = base + (wk << 5) + t;
                float qj = Qin[j * CC + lane];
                float p = 0.f;
#pragma unroll
                for (int c = 0; c < CC; c++)
                    p += __shfl_sync(FULLM, qj, c) * mu[c * CC + lane];
                z0 -= g_e[j * KK]     * p;
                z1 -= g_e[j * KK + 1] * p;
            }
        }
    }
    float e0 = g_e[row * KK] * kw[0], e1 = g_e[row * KK + 1] * kw[1];
    float logit = (g_unary[row * CC + lane] + e0 * z0 + e1 * z1) * INV_TEMP;
    float m = logit;
#pragma unroll
    for (int o = 16; o; o >>= 1) m = fmaxf(m, __shfl_xor_sync(FULLM, m, o));
    float ex = expf(logit - m);
    float s = ex;
#pragma unroll
    for (int o = 16; o; o >>= 1) s += __shfl_xor_sync(FULLM, s, o);
    Qout[row * CC + lane] = ex / s;
}

// ------------- K7: AQ = adj @ Q, 256x32 tile, 8x4/thread fp32x2 -------------
__global__ void __launch_bounds__(256, 1) k_AQ_dense(int sel) {
    const float* Qf = qsel(sel);
    extern __shared__ float sm[];
    float* As  = sm;                      // [KC][256]
    float* Bs2 = sm + KC * 256;           // [KC][BSTRIDE_A] duplicated, padded
    int b = blockIdx.y, chunk = blockIdx.x;
    int tid = threadIdx.x;
    int tx = tid & 7, ty = tid >> 3;      // tx: 4 cols, ty: 8 rows
    int rowbase = b * NN + chunk * 256;
    u64 acc[4][4];
#pragma unroll
    for (int i = 0; i < 4; i++)
#pragma unroll
        for (int j = 0; j < 4; j++) acc[i][j] = 0ull;

    const unsigned* abase = g_adjb + (size_t)rowbase * 32;

    for (int kc = 0; kc < 16; kc++) {
        __syncthreads();
        unsigned w0 = abase[(size_t)tid * 32 + kc * 2];
        unsigned w1 = abase[(size_t)tid * 32 + kc * 2 + 1];
#pragma unroll
        for (int bit = 0; bit < 32; bit++) {
            As[bit * 256 + tid]        = (float)((w0 >> bit) & 1);
            As[(32 + bit) * 256 + tid] = (float)((w1 >> bit) & 1);
        }
        {
            const float4* src = (const float4*)(Qf + (size_t)(b * NN + kc * 64) * CC);
#pragma unroll
            for (int q = 0; q < 2; q++) {
                int j = tid + q * 256;               // 512 float4s
                float4 v = src[j];
                int r = j >> 3, c4 = (j & 7) * 4;    // cols c4..c4+3 = one 4-group
                int g = c4 >> 2;
                float* dst = &Bs2[r * BSTRIDE_A + g * BSLOT_A];
                *(float4*)(dst)     = make_float4(v.x, v.x, v.y, v.y);
                *(float4*)(dst + 4) = make_float4(v.z, v.z, v.w, v.w);
            }
        }
        __syncthreads();

#pragma unroll 4
        for (int k = 0; k < KC; k++) {
            float4 a0 = *(const float4*)&As[k * 256 + ty * 8];
            float4 a1 = *(const float4*)&As[k * 256 + ty * 8 + 4];
            u64 ap[4] = { pack2(a0.x, a0.y), pack2(a0.z, a0.w),
                          pack2(a1.x, a1.y), pack2(a1.z, a1.w) };
            const float* bp = &Bs2[k * BSTRIDE_A + tx * BSLOT_A];
            float4 b0 = *(const float4*)(bp);
            float4 b1 = *(const float4*)(bp + 4);
            u64 bq[4] = { pack2(b0.x, b0.y), pack2(b0.z, b0.w),
                          pack2(b1.x, b1.y), pack2(b1.z, b1.w) };
#pragma unroll
            for (int rp = 0; rp < 4; rp++)
#pragma unroll
                for (int c = 0; c < 4; c++)
                    FMA2(acc[rp][c], ap[rp], bq[c]);
        }
    }

#pragma unroll
    for (int rp = 0; rp < 4; rp++) {
        int r0 = rowbase + ty * 8 + rp * 2;
        float o0[4], o1[4];
#pragma unroll
        for (int c = 0; c < 4; c++) unpack2(acc[rp][c], o0[c], o1[c]);
        *(float4*)&g_AQ[(size_t)r0 * CC + tx * 4]       = make_float4(o0[0], o0[1], o0[2], o0[3]);
        *(float4*)&g_AQ[(size_t)(r0 + 1) * CC + tx * 4] = make_float4(o1[0], o1[1], o1[2], o1[3]);
    }
}

// ------------- K8a: pooled outputs, N-split partials ------------------------
__global__ void k_poolp(int sel) {
    const float* Qf = qsel(sel);
    __shared__ float Qs[64 * 32];
    __shared__ float hs[64 * 64];
    __shared__ float Aq[64 * 32];
    int b = blockIdx.x, nc = blockIdx.y;
    int tid = threadIdx.x;                  // 256
    int n0 = b * NN + nc * 64;
    {
        const float4* sq = (const float4*)(Qf   + (size_t)n0 * CC);
        const float4* sh = (const float4*)(g_h  + (size_t)n0 * HH);
        const float4* sa = (const float4*)(g_AQ + (size_t)n0 * CC);
        ((float4*)Qs)[tid] = sq[tid];  ((float4*)Qs)[tid + 256] = sq[tid + 256];
        ((float4*)Aq)[tid] = sa[tid];  ((float4*)Aq)[tid + 256] = sa[tid + 256];
#pragma unroll
        for (int q = 0; q < 4; q++) ((float4*)hs)[tid + q * 256] = sh[tid + q * 256];
    }
    __syncthreads();
    int tx = tid & 15, ty = tid >> 4;
    float xp[2][4] = {};
    float ap[2][2] = {};
    for (int n = 0; n < 64; n++) {
        float q0 = Qs[n * 32 + ty * 2], q1 = Qs[n * 32 + ty * 2 + 1];
        float4 hv = *(const float4*)&hs[n * 64 + tx * 4];
        float a0 = Aq[n * 32 + tx * 2], a1 = Aq[n * 32 + tx * 2 + 1];
        xp[0][0] += q0 * hv.x; xp[0][1] += q0 * hv.y; xp[0][2] += q0 * hv.z; xp[0][3] += q0 * hv.w;
        xp[1][0] += q1 * hv.x; xp[1][1] += q1 * hv.y; xp[1][2] += q1 * hv.z; xp[1][3] += q1 * hv.w;
        ap[0][0] += q0 * a0; ap[0][1] += q0 * a1;
        ap[1][0] += q1 * a0; ap[1][1] += q1 * a1;
    }
    float* dst = g_poolp + ((size_t)b * 16 + nc) * 3072;
#pragma unroll
    for (int cc = 0; cc < 2; cc++) {
#pragma unroll
        for (int c4 = 0; c4 < 4; c4++)
            dst[(ty * 2 + cc) * 64 + tx * 4 + c4] = xp[cc][c4];
#pragma unroll
        for (int a = 0; a < 2; a++)
            dst[2048 + (ty * 2 + cc) * 32 + tx * 2 + a] = ap[cc][a];
    }
}

// ------------- K8b: reduce pooling partials ---------------------------------
__global__ void k_poolred(float* __restrict__ out) {
    int b = blockIdx.x;
    int idx = blockIdx.y * 256 + threadIdx.x;
    float s = 0.f;
    for (int ch = 0; ch < 16; ch++) s += g_poolp[((size_t)b * 16 + ch) * 3072 + idx];
    if (idx < 2048) {
        int c = idx >> 6, hcol = idx & 63;
        out[((size_t)b * CC + c) * HH + hcol] = s;
    } else {
        int j = idx - 2048, c = j >> 5, a = j & 31;
        out[(size_t)BB * CC * HH + ((size_t)b * CC + c) * CC + a] = s;
    }
}

// ---------------------------------------------------------------------------
extern "C" void kernel_launch(void* const* d_in, const int* in_sizes, int n_in,
                              void* d_out, int out_size) {
    const float* x      = (const float*)d_in[0];
    const int*   adj    = (const int*)  d_in[1];
    const float* Wg     = (const float*)d_in[2];
    const float* bg     = (const float*)d_in[3];
    const float* Wu     = (const float*)d_in[4];
    const float* bu     = (const float*)d_in[5];
    const float* means  = (const float*)d_in[6];
    const float* scales = (const float*)d_in[7];
    const float* kw     = (const float*)d_in[8];
    const float* mu     = (const float*)d_in[9];
    float* out = (float*)d_out;

    const int SMG = (KC * 256 + KC * BSTRIDE_G) * 4;   // 106496 B
    const int SMA = (KC * 256 + KC * BSTRIDE_A) * 4;   //  90112 B
    cudaFuncSetAttribute(k_gcnagg_dense, cudaFuncAttributeMaxDynamicSharedMemorySize, SMG);
    cudaFuncSetAttribute(k_AQ_dense,     cudaFuncAttributeMaxDynamicSharedMemorySize, SMA);

    k_bits        <<<ROWS / 8,  256>>>(adj);
    k_xw          <<<ROWS / 32, 256>>>(x, Wg);
    k_adjl        <<<ROWS / 8,  256>>>();
    k_gcnagg_dense<<<dim3(4, BB), 256, SMG>>>(bg);
    k_unary_e     <<<ROWS / 8,  256>>>(Wu, bu, means, scales);

    int sel = 0;
    for (int it = 0; it < NITER; it++) {
        k_Ycs <<<ROWS / 8, 256>>>(mu, sel);
        k_cs  <<<BB,       64>>>();
        k_msg <<<ROWS / 8, 256>>>(kw, mu, sel);
        sel ^= 1;
    }

    k_AQ_dense <<<dim3(4, BB), 256, SMA>>>(sel);
    k_poolp    <<<dim3(BB, 16), 256>>>(sel);
    k_poolred  <<<dim3(BB, 12), 256>>>(out);
}